// round 11
// baseline (speedup 1.0000x reference)
#include <cuda_runtime.h>
#include <cuda_bf16.h>

// Cascaded 16-tap FIR pair == single 33-tap causal conv for columns i >= 32:
//   y[i] = x[i] + sum_{j=1}^{32} g[j] * x[i-j],  g = [1,h] (*) [1,h_rev]
// Columns [0,32) computed exactly (v-mask aware) by threads 0-1 on row-start tiles.
//
// Persistent CTAs (296 = 2/SM), 128-reg budget: 48-float window + 16 acc +
// all 32 taps register-resident across the loop (no per-tile tap loads).
// Triple-buffered cp.async prefetch -> single __syncthreads per tile.
// smem tile padded 16->20 floats per segment (conflict-free 80B-stride LDS.128).
//
// B=256 rows, N=131072 cols, F=16.

#define F       16
#define GT      33
#define THREADS 256
#define RPT     16
#define TILE    (THREADS * RPT)    // 4096
#define HALO    32
#define NCOL    131072
#define NROW    256
#define TPR     (NCOL / TILE)      // 32 tiles per row
#define NTILES  (TPR * NROW)       // 8192
#define NBLK    296                // 2 per SM

#define SEGP    20                         // 16-float segment padded to 20
#define NSEG    ((TILE + HALO) / 16)       // 258 segments
#define BUFSZ   (NSEG * SEGP)              // 5160 floats = 20640 B
#define NVEC    ((TILE + HALO) / 4)        // 1032 float4 per tile
#define SMEM_DYN (3 * BUFSZ * 4)           // 61920 B

__device__ __forceinline__ void cp16(unsigned dst, const float4* src, int sz) {
    asm volatile("cp.async.cg.shared.global [%0], [%1], 16, %2;"
                 :: "r"(dst), "l"(src), "r"(sz));
}
__device__ __forceinline__ void cp_commit() {
    asm volatile("cp.async.commit_group;");
}
template <int N> __device__ __forceinline__ void cp_wait() {
    asm volatile("cp.async.wait_group %0;" :: "n"(N));
}

// float4 vk -> padded float4 slot (vk>>2)*5 + (vk&3)
__device__ __forceinline__ void stage_tile(unsigned sb, const float* x,
                                           int t, int tid)
{
    const int row = t / TPR;
    const int tir = t % TPR;
    const float4* src = reinterpret_cast<const float4*>(
        x + (size_t)row * NCOL + tir * TILE - HALO);
    const bool z = (tir == 0);
#pragma unroll
    for (int vk = tid; vk < NVEC; vk += THREADS) {
        const int sz = (z && vk < HALO / 4) ? 0 : 16;
        const float4* sp = sz ? (src + vk) : reinterpret_cast<const float4*>(x);
        cp16(sb + (((vk >> 2) * 5 + (vk & 3)) << 4), sp, sz);
    }
}

__global__ __launch_bounds__(THREADS, 2)
void fir2_fused(const float* __restrict__ x,
                const float* __restrict__ h,
                float* __restrict__ y)
{
    extern __shared__ float sx[];          // 3 padded tile buffers
    __shared__ float sg[GT + 3];

    const int tid = threadIdx.x;

    // ---- per-block combined taps (threads 0..32) ----------------------------
    if (tid < GT) {
        const int j = tid;
        float acc = 0.0f;
        const int a0 = (j > F) ? (j - F) : 0;
        const int a1 = (j < F) ? j : F;
        for (int a = a0; a <= a1; a++) {
            const float ka = (a == 0) ? 1.0f : __ldg(h + a - 1);
            const int bb = j - a;
            const float kb = (bb == 0) ? 1.0f : __ldg(h + F - bb);
            acc += ka * kb;
        }
        sg[j] = acc;
    }

    const unsigned sb0 = (unsigned)__cvta_generic_to_shared(sx);

    // ---- prefetch first tile ------------------------------------------------
    int t = blockIdx.x;
    stage_tile(sb0, x, t, tid);
    cp_commit();
    __syncthreads();                       // sg ready

    // taps -> registers, resident for the whole persistent loop
    float gr[GT];
#pragma unroll
    for (int j = 1; j < GT; j++) gr[j] = sg[j];

    int it = 0;
    for (; t < NTILES; t += NBLK, it++) {
        const int bcur = it % 3;
        const int bnxt = (bcur == 2) ? 0 : bcur + 1;

        const int tn = t + NBLK;
        if (tn < NTILES) stage_tile(sb0 + bnxt * (BUFSZ * 4), x, tn, tid);
        cp_commit();
        cp_wait<1>();                      // current tile's group complete
        __syncthreads();                   // single barrier per tile (3 bufs)

        const int row = t / TPR;
        const int tir = t % TPR;
        const int t0  = tir * TILE;
        const size_t rowoff = (size_t)row * NCOL;
        const float* sxc = sx + bcur * BUFSZ;

        if (!(tir == 0 && tid < 2)) {
            // window: w[c] = x[row][t0 + tid*16 - 32 + c], c in [0,48)
            float w[RPT + HALO];
            {
                const int k0 = tid * RPT;
#pragma unroll
                for (int q = 0; q < 12; q++) {
                    const int k = k0 + 4 * q;
                    *reinterpret_cast<float4*>(&w[4 * q]) =
                        *reinterpret_cast<const float4*>(
                            &sxc[(k >> 4) * SEGP + (k & 15)]);
                }
            }

            float acc[RPT];
#pragma unroll
            for (int r = 0; r < RPT; r++) acc[r] = w[r + 32];   // identity tap

#pragma unroll
            for (int j = 1; j < GT; j++) {
#pragma unroll
                for (int r = 0; r < RPT; r++)
                    acc[r] = fmaf(gr[j], w[r + 32 - j], acc[r]);
            }

            float4* yo = reinterpret_cast<float4*>(y + rowoff + t0 + tid * RPT);
#pragma unroll
            for (int q = 0; q < 4; q++)
                yo[q] = make_float4(acc[4 * q], acc[4 * q + 1],
                                    acc[4 * q + 2], acc[4 * q + 3]);
        } else {
            // ---- exact masked two-stage result for columns [0,32) ----------
            if (tid == 0) {
                float4* yo = reinterpret_cast<float4*>(y + rowoff);
#pragma unroll
                for (int q = 0; q < 4; q++)
                    yo[q] = make_float4(0.f, 0.f, 0.f, 0.f);   // y[0..15] = 0
            } else {
                const float* xr = x + rowoff;
                float xa[32];
#pragma unroll
                for (int c = 0; c < 32; c++) xa[c] = xr[c];
                float hh[F];
#pragma unroll
                for (int j = 0; j < F; j++) hh[j] = __ldg(h + j);

                float va[F];           // v[16..31]
#pragma unroll
                for (int tt = 0; tt < F; tt++) {
                    const int k = F + tt;
                    float a2 = xa[k];
#pragma unroll
                    for (int j = 0; j < F; j++)
                        a2 = fmaf(hh[j], xa[k - 1 - j], a2);
                    va[tt] = a2;
                }
                float ya[F];           // y[16..31]
#pragma unroll
                for (int tt = 0; tt < F; tt++) {
                    const int i = F + tt;
                    float a2 = va[tt];
#pragma unroll
                    for (int m = 0; m < F; m++) {
                        const int k = i - F + m;   // v index; masked if < 16
                        if (k >= F) a2 = fmaf(hh[m], va[k - F], a2);
                    }
                    ya[tt] = a2;
                }
                float4* yo = reinterpret_cast<float4*>(y + rowoff + F);
#pragma unroll
                for (int q = 0; q < 4; q++)
                    yo[q] = make_float4(ya[4 * q], ya[4 * q + 1],
                                        ya[4 * q + 2], ya[4 * q + 3]);
            }
        }
        // no end-of-loop barrier: with 3 buffers, the next write to any
        // buffer is separated from its last read by two intervening
        // __syncthreads (iters i-1 and i), so WAR is safe.
    }
}

extern "C" void kernel_launch(void* const* d_in, const int* in_sizes, int n_in,
                              void* d_out, int out_size)
{
    const float* x = (const float*)d_in[0];   // (256, 131072) f32
    const float* h = (const float*)d_in[1];   // (1, 16) f32
    float* y = (float*)d_out;                 // (256, 131072) f32

    cudaFuncSetAttribute(fir2_fused,
                         cudaFuncAttributeMaxDynamicSharedMemorySize, SMEM_DYN);
    fir2_fused<<<NBLK, THREADS, SMEM_DYN>>>(x, h, y);
}

// round 12
// speedup vs baseline: 1.2309x; 1.2309x over previous
#include <cuda_runtime.h>
#include <cuda_bf16.h>

// Cascaded 16-tap FIR pair == single 33-tap causal conv for columns i >= 32:
//   y[i] = x[i] + sum_{j=1}^{32} g[j] * x[i-j],  g = [1,h] (*) [1,h_rev]
// Columns [0,32) computed exactly (v-mask aware) by lanes 0-1 on row-start tiles.
//
// BARRIER-FREE warp-stream design: each warp is an independent persistent
// stream over 512-float warp-tiles with a private double-buffered smem slice
// filled by its own cp.async groups (per-thread group state -> no block sync
// anywhere). Warps drift out of phase, overlapping LDS bursts of one warp
// with FFMA of the others. Taps computed per-thread in registers at start.
//
// B=256 rows, N=131072 cols, F=16.

#define F       16
#define GT      33
#define THREADS 256
#define WARPS   8
#define RPT     16
#define WTILE   512                // floats per warp-tile
#define HALO    32
#define NCOL    131072
#define NROW    256
#define WPR     (NCOL / WTILE)     // 256 warp-tiles per row
#define NWT     (WPR * NROW)       // 65536 warp-tiles
#define NBLK    296                // 2 CTAs per SM
#define NSTREAM (NBLK * WARPS)     // 2368 warp streams

#define SEGP    20                         // 16-float segment padded to 20
#define NSEG    ((WTILE + HALO) / 16)      // 34 segments
#define BUFW    (NSEG * SEGP)              // 680 floats per buffer
#define NVEC    ((WTILE + HALO) / 4)       // 136 float4 per warp-tile

__device__ __forceinline__ void cp16(unsigned dst, const float4* src, int sz) {
    asm volatile("cp.async.cg.shared.global [%0], [%1], 16, %2;"
                 :: "r"(dst), "l"(src), "r"(sz));
}
__device__ __forceinline__ void cp_commit() {
    asm volatile("cp.async.commit_group;");
}
template <int N> __device__ __forceinline__ void cp_wait() {
    asm volatile("cp.async.wait_group %0;" :: "n"(N));
}

// Stage one warp-tile (512 floats + 32 halo) into this warp's padded buffer.
// float4 vk -> padded float4 slot (vk>>2)*5 + (vk&3). Lanes cover vk = lane+32k.
__device__ __forceinline__ void stage_wt(unsigned sb, const float* x,
                                         int wt, int lane)
{
    const int row = wt / WPR;
    const int tir = wt % WPR;
    const float4* src = reinterpret_cast<const float4*>(
        x + (size_t)row * NCOL + tir * WTILE - HALO);
    const bool z = (tir == 0);
#pragma unroll
    for (int vk = lane; vk < NVEC; vk += 32) {
        const int sz = (z && vk < HALO / 4) ? 0 : 16;
        const float4* sp = sz ? (src + vk) : reinterpret_cast<const float4*>(x);
        cp16(sb + (((vk >> 2) * 5 + (vk & 3)) << 4), sp, sz);
    }
}

__global__ __launch_bounds__(THREADS, 2)
void fir2_fused(const float* __restrict__ x,
                const float* __restrict__ h,
                float* __restrict__ y)
{
    __shared__ float sx[WARPS * 2 * BUFW];   // per-warp double buffers

    const int tid  = threadIdx.x;
    const int wid  = tid >> 5;
    const int lane = tid & 31;

    // ---- taps in registers, computed once per thread ------------------------
    float hh[F];
#pragma unroll
    for (int j = 0; j < F; j++) hh[j] = __ldg(h + j);

    float gr[GT];                            // gr[1..32]; gr[0]=1 implicit
#pragma unroll
    for (int j = 1; j < GT; j++) {
        float acc = 0.0f;
        const int a0 = (j > F) ? (j - F) : 0;
        const int a1 = (j < F) ? j : F;
#pragma unroll
        for (int a = 0; a <= F; a++) {
            if (a >= a0 && a <= a1) {
                const float ka = (a == 0) ? 1.0f : hh[a - 1];
                const int bb = j - a;
                const float kb = (bb == 0) ? 1.0f : hh[F - bb];
                acc += ka * kb;
            }
        }
        gr[j] = acc;
    }

    // per-warp buffer base addresses (shared-window addresses for cp.async)
    const unsigned sbw = (unsigned)__cvta_generic_to_shared(sx)
                       + (unsigned)(wid * 2 * BUFW) * 4u;
    float* const bptr = sx + wid * 2 * BUFW;

    // ---- warp-stream persistent loop ---------------------------------------
    int wt = blockIdx.x * WARPS + wid;
    if (wt < NWT) { stage_wt(sbw, x, wt, lane); }
    cp_commit();

    int buf = 0;
    for (; wt < NWT; wt += NSTREAM, buf ^= 1) {
        const int wtn = wt + NSTREAM;
        if (wtn < NWT) stage_wt(sbw + (buf ^ 1) * (BUFW * 4), x, wtn, lane);
        cp_commit();
        cp_wait<1>();                        // current buffer's group landed
        __syncwarp();

        const int row = wt / WPR;
        const int tir = wt % WPR;
        const int t0  = tir * WTILE;
        const size_t rowoff = (size_t)row * NCOL;
        const float* sxc = bptr + buf * BUFW;

        if (!(tir == 0 && lane < 2)) {
            // window: w[c] = x[row][t0 + lane*16 - 32 + c], c in [0,48)
            float w[RPT + HALO];
            {
                const int k0 = lane * RPT;
#pragma unroll
                for (int q = 0; q < 12; q++) {
                    const int k = k0 + 4 * q;
                    *reinterpret_cast<float4*>(&w[4 * q]) =
                        *reinterpret_cast<const float4*>(
                            &sxc[(k >> 4) * SEGP + (k & 15)]);
                }
            }

            float acc[RPT];
#pragma unroll
            for (int r = 0; r < RPT; r++) acc[r] = w[r + 32];   // identity tap

#pragma unroll
            for (int j = 1; j < GT; j++) {
#pragma unroll
                for (int r = 0; r < RPT; r++)
                    acc[r] = fmaf(gr[j], w[r + 32 - j], acc[r]);
            }

            float4* yo = reinterpret_cast<float4*>(y + rowoff + t0 + lane * RPT);
#pragma unroll
            for (int q = 0; q < 4; q++)
                yo[q] = make_float4(acc[4 * q], acc[4 * q + 1],
                                    acc[4 * q + 2], acc[4 * q + 3]);
        } else {
            // ---- exact masked two-stage result for columns [0,32) ----------
            if (lane == 0) {
                float4* yo = reinterpret_cast<float4*>(y + rowoff);
#pragma unroll
                for (int q = 0; q < 4; q++)
                    yo[q] = make_float4(0.f, 0.f, 0.f, 0.f);   // y[0..15] = 0
            } else {
                const float* xr = x + rowoff;
                float xa[32];
#pragma unroll
                for (int c = 0; c < 32; c++) xa[c] = xr[c];

                float va[F];           // v[16..31]
#pragma unroll
                for (int tt = 0; tt < F; tt++) {
                    const int k = F + tt;
                    float a2 = xa[k];
#pragma unroll
                    for (int j = 0; j < F; j++)
                        a2 = fmaf(hh[j], xa[k - 1 - j], a2);
                    va[tt] = a2;
                }
                float ya[F];           // y[16..31]
#pragma unroll
                for (int tt = 0; tt < F; tt++) {
                    const int i = F + tt;
                    float a2 = va[tt];
#pragma unroll
                    for (int m = 0; m < F; m++) {
                        const int k = i - F + m;   // v index; masked if < 16
                        if (k >= F) a2 = fmaf(hh[m], va[k - F], a2);
                    }
                    ya[tt] = a2;
                }
                float4* yo = reinterpret_cast<float4*>(y + rowoff + F);
#pragma unroll
                for (int q = 0; q < 4; q++)
                    yo[q] = make_float4(ya[4 * q], ya[4 * q + 1],
                                        ya[4 * q + 2], ya[4 * q + 3]);
            }
        }
        // No block barrier. WAR safety: in-order issue per warp guarantees all
        // LDS reads of this buffer complete (their FFMA consumers issued)
        // before the next cp.async write to it can issue.
    }
}

extern "C" void kernel_launch(void* const* d_in, const int* in_sizes, int n_in,
                              void* d_out, int out_size)
{
    const float* x = (const float*)d_in[0];   // (256, 131072) f32
    const float* h = (const float*)d_in[1];   // (1, 16) f32
    float* y = (float*)d_out;                 // (256, 131072) f32

    fir2_fused<<<NBLK, THREADS>>>(x, h, y);
}